// round 6
// baseline (speedup 1.0000x reference)
#include <cuda_runtime.h>
#include <cstdint>

#define BATCH 16
#define NPROP 2048
#define NCLS 80
#define NCLS1 81
#define KTOP 2048
#define CAP 16384
#define SCORE_THR 0.05f
#define IOU_THR 0.5f
#define MAXR 4.135166556742356f
#define OUTK 100
#define BINS 2304
#define HISTN 3072
#define SLOTS 4096
#define NT 1024

typedef unsigned long long ull;

// ---------------- device scratch ----------------
__device__ ull g_keys[BATCH][CAP];
__device__ int g_cnt[BATCH];   // zero-init at load; re-zeroed at end of k_fused

__device__ __forceinline__ int score_bin(unsigned u) {
    int bn = (int)(u >> 14) - 62770;
    return min(max(bn, 0), BINS - 1);
}

// ---------------- 1: softmax + threshold compaction ----------------
__global__ void k_softmax_compact(const float* __restrict__ cls) {
    int gw = (blockIdx.x * blockDim.x + threadIdx.x) >> 5;
    int lane = threadIdx.x & 31;
    if (gw >= BATCH * NPROP) return;
    int b = gw >> 11;
    int n = gw & (NPROP - 1);
    const float* x = cls + (size_t)gw * NCLS1;
    float v0 = x[lane];
    float v1 = x[lane + 32];
    float v2 = (lane < 17) ? x[lane + 64] : -3.4e38f;
    float m = fmaxf(fmaxf(v0, v1), v2);
#pragma unroll
    for (int o = 16; o > 0; o >>= 1) m = fmaxf(m, __shfl_xor_sync(0xffffffffu, m, o));
    float e0 = expf(v0 - m);
    float e1 = expf(v1 - m);
    float e2 = (lane < 17) ? expf(v2 - m) : 0.0f;
    float s = e0 + e1 + e2;
#pragma unroll
    for (int o = 16; o > 0; o >>= 1) s += __shfl_xor_sync(0xffffffffu, s, o);

    auto push = [&](bool cond, float p, unsigned idx) {
        unsigned mask = __ballot_sync(0xffffffffu, cond);
        if (cond) {
            unsigned u = __float_as_uint(p);
            int leader = __ffs(mask) - 1;
            int base = 0;
            if (lane == leader) base = atomicAdd(&g_cnt[b], __popc(mask));
            base = __shfl_sync(mask, base, leader);
            int pos = base + __popc(mask & ((1u << lane) - 1));
            if (pos < CAP)
                g_keys[b][pos] = ((ull)(~u) << 32) | idx;
        }
    };
    float p0 = e0 / s;
    push(p0 > SCORE_THR, p0, (unsigned)(n * NCLS + lane));
    float p1 = e1 / s;
    push(p1 > SCORE_THR, p1, (unsigned)(n * NCLS + lane + 32));
    float p2 = e2 / s;  // 0 for lane>=17
    push((lane < 16) && (p2 > SCORE_THR), p2, (unsigned)(n * NCLS + lane + 64));
}

// ---------------- 2: fused hist + counting-sort(rank) + decode + NMS + output ----------------
// dynamic smem layout (bytes):
//   [0      , 32768 )  ull    skey[SLOTS]    final sorted keys
//   [32768  , 65536 )  ull    tmpk[SLOTS]    bin-grouped scatter
//   [65536  , 98304 )  float4 sbox[KTOP]     class-offset boxes
//   [98304  , 131072)  float4 sbxout[KTOP]   clipped boxes for output
//   [131072 , 139264)  float  sarea[KTOP]
//   [139264 , 151552)  int    hist[HISTN]    (reused as ctr)
//   [151552 , 163840)  int    base[HISTN]
#define SMEM_DYN 163840
extern __shared__ char dyn[];

__global__ void __launch_bounds__(NT) k_fused(const float* __restrict__ reg,
                                              const float* __restrict__ props,
                                              const int* __restrict__ hw,
                                              float* __restrict__ out) {
    int b = blockIdx.x;
    int tid = threadIdx.x;
    int lane = tid & 31;
    int warp = tid >> 5;

    ull* skey = (ull*)dyn;
    ull* tmpk = (ull*)(dyn + 32768);
    float4* sbox = (float4*)(dyn + 65536);
    float4* sbxout = (float4*)(dyn + 98304);
    float* sarea = (float*)(dyn + 131072);
    int* hist = (int*)(dyn + 139264);
    int* base = (int*)(dyn + 151552);

    __shared__ int s_wsum[32];
    __shared__ unsigned a32[KTOP / 32];
    __shared__ int s_keep[OUTK];

    int cnt = min(g_cnt[b], CAP);

    // ---- smem histogram from keys ----
    for (int i = tid; i < HISTN; i += NT) hist[i] = 0;
    __syncthreads();
    for (int i = tid; i < cnt; i += NT) {
        ull k = g_keys[b][i];
        atomicAdd(&hist[score_bin(~(unsigned)(k >> 32))], 1);
    }
    __syncthreads();

    // ---- hierarchical suffix scan: base[bb] = # candidates in bins > bb ----
    int h0 = hist[3 * tid], h1 = hist[3 * tid + 1], h2 = hist[3 * tid + 2];
    int loc = h0 + h1 + h2;
    int v = loc;
#pragma unroll
    for (int o = 1; o < 32; o <<= 1) {
        int u = __shfl_down_sync(0xffffffffu, v, o);
        if (lane + o < 32) v += u;
    }
    if (lane == 0) s_wsum[warp] = v;
    __syncthreads();
    if (warp == 0) {
        int wv = s_wsum[lane];
#pragma unroll
        for (int o = 1; o < 32; o <<= 1) {
            int u = __shfl_down_sync(0xffffffffu, wv, o);
            if (lane + o < 32) wv += u;
        }
        s_wsum[lane] = wv;
    }
    __syncthreads();
    int beyondW = (warp < 31) ? s_wsum[warp + 1] : 0;
    int beyond = v + beyondW - loc;   // candidates in chunks > tid
    base[3 * tid + 2] = beyond;
    base[3 * tid + 1] = beyond + h2;
    base[3 * tid] = beyond + h2 + h1;
    int S_total = s_wsum[0];
    __syncthreads();

    // ---- reset hist as ctr ----
    for (int i = tid; i < HISTN; i += NT) hist[i] = 0;
    __syncthreads();

    // ---- scatter to bin-grouped tmp slots ----
    for (int i = tid; i < cnt; i += NT) {
        ull k = g_keys[b][i];
        int bb = score_bin(~(unsigned)(k >> 32));
        int st = base[bb];
        if (st >= SLOTS) continue;
        int pos = st + atomicAdd(&hist[bb], 1);
        if (pos < SLOTS) tmpk[pos] = k;
    }
    __syncthreads();

    // ---- parallel exact-rank placement (only bins intersecting top-2048) ----
    int S_use = min(S_total, SLOTS);
    for (int i = tid; i < S_use; i += NT) {
        ull k = tmpk[i];
        int bb = score_bin(~(unsigned)(k >> 32));
        int st = base[bb];
        if (st >= KTOP) continue;
        int en = min(st + hist[bb], SLOTS);
        int r = 0;
        for (int j = st; j < en; j++) r += (tmpk[j] < k);
        int pos = st + r;
        if (pos < SLOTS) skey[pos] = k;
    }
    __syncthreads();

    int validcnt = min(S_total, KTOP);

    // ---- decode top-2048 ----
    float h = (float)hw[b * 2];
    float w = (float)hw[b * 2 + 1];
    float offmul = fmaxf(w, h) + 1.0f;

    for (int i = tid; i < KTOP; i += NT) {
        if (i >= validcnt) {
            sbox[i] = make_float4(-1e9f, -1e9f, -1e9f, -1e9f);
            sbxout[i] = make_float4(0.f, 0.f, 0.f, 0.f);
            sarea[i] = 0.f;
            continue;
        }
        ull key = skey[i];
        unsigned idx = (unsigned)key;
        int n = (int)(idx / NCLS);
        int c = (int)(idx % NCLS);
        const float* pr = props + ((size_t)b * NPROP + n) * 4;
        float p0 = pr[0], p1 = pr[1], p2 = pr[2], p3 = pr[3];
        float px = (p0 + p2) * 0.5f;
        float py = (p1 + p3) * 0.5f;
        float pw = p2 - p0;
        float ph = p3 - p1;
        const float* dd = reg + ((size_t)b * NPROP + n) * (NCLS * 4) + c * 4;
        float dx = dd[0] * 0.1f;
        float dy = dd[1] * 0.1f;
        float dw = fminf(fmaxf(dd[2] * 0.2f, -MAXR), MAXR);
        float dh = fminf(fmaxf(dd[3] * 0.2f, -MAXR), MAXR);
        float gw = pw * expf(dw);
        float gh = ph * expf(dh);
        float gx = px + pw * dx;
        float gy = py + ph * dy;
        float x1 = fminf(fmaxf(gx - 0.5f * gw, 0.f), w);
        float y1 = fminf(fmaxf(gy - 0.5f * gh, 0.f), h);
        float x2 = fminf(fmaxf(gx + 0.5f * gw, 0.f), w);
        float y2 = fminf(fmaxf(gy + 0.5f * gh, 0.f), h);
        float off = (float)c * offmul;
        sbxout[i] = make_float4(x1, y1, x2, y2);
        float4 sbv = make_float4(x1 + off, y1 + off, x2 + off, y2 + off);
        sbox[i] = sbv;
        sarea[i] = fmaxf(sbv.z - sbv.x, 0.f) * fmaxf(sbv.w - sbv.y, 0.f);
    }

    // ---- alive init ----
    {
        unsigned b1 = __ballot_sync(0xffffffffu, tid < validcnt);
        if (lane == 0) a32[tid >> 5] = b1;
        unsigned b2 = __ballot_sync(0xffffffffu, tid + 1024 < validcnt);
        if (lane == 0) a32[32 + (tid >> 5)] = b2;
    }
    __syncthreads();

    // ---- greedy NMS: 1 barrier/iter, redundant per-warp search, alive-skip ----
    int cur = -1;
    int kc = 0;
    for (;;) {
        ull ww = ((ull)a32[2 * lane]) | (((ull)a32[2 * lane + 1]) << 32);
        int basebit = lane << 6;
        if (cur >= basebit) {
            int k2 = cur - basebit;
            ww = (k2 >= 63) ? 0ULL : (ww & ~((2ULL << k2) - 1ULL));
        }
        unsigned bal = __ballot_sync(0xffffffffu, ww != 0ULL);
        int i = -1;
        if (bal) {
            int ln = __ffs(bal) - 1;
            ull w2 = __shfl_sync(0xffffffffu, ww, ln);
            i = (ln << 6) + __ffsll((long long)w2) - 1;
        }
        if (i < 0) break;
        if (tid == 0) s_keep[kc] = i;
        kc++;
        cur = i;
        if (kc >= OUTK) break;

        float4 A = sbox[i];
        float areaA = sarea[i];
        {
            int j = tid;
            unsigned aw = a32[j >> 5];
            bool sup = false;
            if (j > i && ((aw >> (j & 31)) & 1u)) {
                float4 q = sbox[j];
                float inter = fmaxf(fminf(A.z, q.z) - fmaxf(A.x, q.x), 0.f) *
                              fmaxf(fminf(A.w, q.w) - fmaxf(A.y, q.y), 0.f);
                float uni = areaA + sarea[j] - inter;
                sup = (uni > 0.f) && (inter > IOU_THR * uni);
            }
            unsigned sb_ = __ballot_sync(0xffffffffu, sup);
            if (lane == 0 && sb_) a32[j >> 5] = aw & ~sb_;
        }
        {
            int j = tid + 1024;
            unsigned aw = a32[j >> 5];
            bool sup = false;
            if (j > i && ((aw >> (j & 31)) & 1u)) {
                float4 q = sbox[j];
                float inter = fmaxf(fminf(A.z, q.z) - fmaxf(A.x, q.x), 0.f) *
                              fmaxf(fminf(A.w, q.w) - fmaxf(A.y, q.y), 0.f);
                float uni = areaA + sarea[j] - inter;
                sup = (uni > 0.f) && (inter > IOU_THR * uni);
            }
            unsigned sb_ = __ballot_sync(0xffffffffu, sup);
            if (lane == 0 && sb_) a32[j >> 5] = aw & ~sb_;
        }
        __syncthreads();
    }
    __syncthreads();  // s_keep visibility

    // ---- output ----
    for (int r = tid; r < OUTK; r += NT) {
        if (r < kc) {
            int i = s_keep[r];
            ull key = skey[i];
            ((float4*)out)[b * OUTK + r] = sbxout[i];
            out[BATCH * OUTK * 4 + b * OUTK + r] = __uint_as_float(~(unsigned)(key >> 32));
            out[BATCH * OUTK * 5 + b * OUTK + r] = (float)((unsigned)key % NCLS);
        } else {
            ((float4*)out)[b * OUTK + r] = make_float4(0.f, 0.f, 0.f, 0.f);
            out[BATCH * OUTK * 4 + b * OUTK + r] = 0.0f;
            out[BATCH * OUTK * 5 + b * OUTK + r] = -1.0f;
        }
    }

    // ---- reset g_cnt for next launch (deterministic: every launch starts at 0) ----
    if (tid == 0) g_cnt[b] = 0;
}

// ---------------- launch ----------------
extern "C" void kernel_launch(void* const* d_in, const int* in_sizes, int n_in,
                              void* d_out, int out_size) {
    const float* cls = (const float*)d_in[0];   // [16,2048,81]
    const float* reg = (const float*)d_in[1];   // [16,2048,320]
    const float* props = (const float*)d_in[2]; // [16,2048,4]
    const int* hw = (const int*)d_in[3];        // [16,2]
    float* out = (float*)d_out;

    cudaFuncSetAttribute(k_fused,
                         cudaFuncAttributeMaxDynamicSharedMemorySize, SMEM_DYN);

    k_softmax_compact<<<(BATCH * NPROP * 32) / 256, 256>>>(cls);
    k_fused<<<BATCH, NT, SMEM_DYN>>>(reg, props, hw, out);
}

// round 7
// speedup vs baseline: 1.8933x; 1.8933x over previous
#include <cuda_runtime.h>
#include <cstdint>

#define BATCH 16
#define NPROP 2048
#define NCLS 80
#define NCLS1 81
#define KTOP 2048
#define CAP 16384
#define SCORE_THR 0.05f
#define IOU_THR 0.5f
#define MAXR 4.135166556742356f
#define OUTK 100
#define HISTN 3072
#define BINS 2304
#define SLOTS 4096
#define NT 1024

typedef unsigned long long ull;

// ---------------- device scratch ----------------
__device__ ull g_keys[BATCH][CAP];
__device__ int g_cnt[BATCH];   // zero-init at load; re-zeroed at end of k_fused

__device__ __forceinline__ int score_bin(unsigned u) {
    int bn = (int)(u >> 14) - 62770;
    return min(max(bn, 0), BINS - 1);
}

// ---------------- 1: softmax + threshold + block-aggregated compaction ----------------
// 256 threads = 8 warps = 8 proposals, all same image.
__global__ void k_softmax_compact(const float* __restrict__ cls) {
    __shared__ int s_cnt, s_base;
    __shared__ ull s_buf[176];   // hard bound: 8 proposals * 19 = 152
    int tid = threadIdx.x;
    int lane = tid & 31;
    int w = tid >> 5;
    int gw = blockIdx.x * 8 + w;            // global proposal
    int b = gw >> 11;
    int n = gw & (NPROP - 1);

    if (tid == 0) s_cnt = 0;
    __syncthreads();

    const float* x = cls + (size_t)gw * NCLS1;
    float v0 = x[lane];
    float v1 = x[lane + 32];
    float v2 = (lane < 17) ? x[lane + 64] : -3.4e38f;
    float m = fmaxf(fmaxf(v0, v1), v2);
#pragma unroll
    for (int o = 16; o > 0; o >>= 1) m = fmaxf(m, __shfl_xor_sync(0xffffffffu, m, o));
    float e0 = expf(v0 - m);
    float e1 = expf(v1 - m);
    float e2 = (lane < 17) ? expf(v2 - m) : 0.0f;
    float s = e0 + e1 + e2;
#pragma unroll
    for (int o = 16; o > 0; o >>= 1) s += __shfl_xor_sync(0xffffffffu, s, o);

    auto push = [&](bool cond, float p, unsigned idx) {
        unsigned mask = __ballot_sync(0xffffffffu, cond);
        if (cond) {
            unsigned u = __float_as_uint(p);
            int leader = __ffs(mask) - 1;
            int base = 0;
            if (lane == leader) base = atomicAdd(&s_cnt, __popc(mask));
            base = __shfl_sync(mask, base, leader);
            s_buf[base + __popc(mask & ((1u << lane) - 1))] = ((ull)(~u) << 32) | idx;
        }
    };
    float p0 = e0 / s;
    push(p0 > SCORE_THR, p0, (unsigned)(n * NCLS + lane));
    float p1 = e1 / s;
    push(p1 > SCORE_THR, p1, (unsigned)(n * NCLS + lane + 32));
    float p2 = e2 / s;
    push((lane < 16) && (p2 > SCORE_THR), p2, (unsigned)(n * NCLS + lane + 64));
    __syncthreads();

    if (tid == 0) s_base = atomicAdd(&g_cnt[b], s_cnt);
    __syncthreads();
    int cnt = s_cnt, base = s_base;
    for (int i = tid; i < cnt; i += 256)
        if (base + i < CAP) g_keys[b][base + i] = s_buf[i];
}

// ---------------- 2: fused sort + decode + per-class NMS + output ----------------
// dynamic smem layout (bytes):
//   [0      , 32768 )  ull    skey[SLOTS]
//   [32768  , 65536 )  ull    tmpk[SLOTS]  -- after rank placement reused as:
//        [32768, 40960)  int  clist[KTOP]
//        [40960, 43008)  char slab[KTOP]
//        [43008, 45056)  char salive[KTOP]
//   [65536  , 98304 )  float4 sbox[KTOP]
//   [98304  , 131072)  float4 sbxout[KTOP]
//   [131072 , 139264)  float  sarea[KTOP]
//   [139264 , 151552)  int    hist[HISTN]
//   [151552 , 163840)  int    base[HISTN]
#define SMEM_DYN 163840
extern __shared__ char dyn[];

__global__ void __launch_bounds__(NT) k_fused(const float* __restrict__ reg,
                                              const float* __restrict__ props,
                                              const int* __restrict__ hw,
                                              float* __restrict__ out) {
    int b = blockIdx.x;
    int tid = threadIdx.x;
    int lane = tid & 31;
    int warp = tid >> 5;

    ull* skey = (ull*)dyn;
    ull* tmpk = (ull*)(dyn + 32768);
    int* clist = (int*)(dyn + 32768);
    char* slab = (char*)(dyn + 40960);
    char* salive = (char*)(dyn + 43008);
    float4* sbox = (float4*)(dyn + 65536);
    float4* sbxout = (float4*)(dyn + 98304);
    float* sarea = (float*)(dyn + 131072);
    int* hist = (int*)(dyn + 139264);
    int* base = (int*)(dyn + 151552);

    __shared__ int s_wsum[32];
    __shared__ int c_cnt[NCLS], c_base[NCLS];
    __shared__ int s_total;

    int cnt = min(g_cnt[b], CAP);

    // ---- smem histogram from keys ----
    for (int i = tid; i < HISTN; i += NT) hist[i] = 0;
    __syncthreads();
    for (int i = tid; i < cnt; i += NT)
        atomicAdd(&hist[score_bin(~(unsigned)(g_keys[b][i] >> 32))], 1);
    __syncthreads();

    // ---- hierarchical suffix scan: base[bb] = # candidates in bins > bb ----
    int h0 = hist[3 * tid], h1 = hist[3 * tid + 1], h2 = hist[3 * tid + 2];
    int loc = h0 + h1 + h2;
    int v = loc;
#pragma unroll
    for (int o = 1; o < 32; o <<= 1) {
        int u = __shfl_down_sync(0xffffffffu, v, o);
        if (lane + o < 32) v += u;
    }
    if (lane == 0) s_wsum[warp] = v;
    __syncthreads();
    if (warp == 0) {
        int wv = s_wsum[lane];
#pragma unroll
        for (int o = 1; o < 32; o <<= 1) {
            int u = __shfl_down_sync(0xffffffffu, wv, o);
            if (lane + o < 32) wv += u;
        }
        s_wsum[lane] = wv;
    }
    __syncthreads();
    int beyondW = (warp < 31) ? s_wsum[warp + 1] : 0;
    int beyond = v + beyondW - loc;
    base[3 * tid + 2] = beyond;
    base[3 * tid + 1] = beyond + h2;
    base[3 * tid] = beyond + h2 + h1;
    int S_total = s_wsum[0];
    __syncthreads();

    // ---- reset hist as ctr, scatter to bin-grouped slots ----
    for (int i = tid; i < HISTN; i += NT) hist[i] = 0;
    __syncthreads();
    for (int i = tid; i < cnt; i += NT) {
        ull k = g_keys[b][i];
        int bb = score_bin(~(unsigned)(k >> 32));
        int st = base[bb];
        if (st >= SLOTS) continue;
        int pos = st + atomicAdd(&hist[bb], 1);
        if (pos < SLOTS) tmpk[pos] = k;
    }
    __syncthreads();

    // ---- parallel exact-rank placement (bins intersecting top-2048) ----
    int S_use = min(S_total, SLOTS);
    for (int i = tid; i < S_use; i += NT) {
        ull k = tmpk[i];
        int bb = score_bin(~(unsigned)(k >> 32));
        int st = base[bb];
        if (st >= KTOP) continue;
        int en = min(st + hist[bb], SLOTS);
        int r = 0;
        for (int j = st; j < en; j++) r += (tmpk[j] < k);
        int pos = st + r;
        if (pos < SLOTS) skey[pos] = k;
    }
    __syncthreads();

    int validcnt = min(S_total, KTOP);

    // ---- decode top-2048 (clobbers tmpk region with slab/salive) ----
    float h = (float)hw[b * 2];
    float w = (float)hw[b * 2 + 1];
    float offmul = fmaxf(w, h) + 1.0f;

    for (int i = tid; i < KTOP; i += NT) {
        if (i >= validcnt) { salive[i] = 0; continue; }
        ull key = skey[i];
        unsigned idx = (unsigned)key;
        int n = (int)(idx / NCLS);
        int c = (int)(idx % NCLS);
        const float* pr = props + ((size_t)b * NPROP + n) * 4;
        float p0 = pr[0], p1 = pr[1], p2 = pr[2], p3 = pr[3];
        float px = (p0 + p2) * 0.5f;
        float py = (p1 + p3) * 0.5f;
        float pw = p2 - p0;
        float ph = p3 - p1;
        const float* dd = reg + ((size_t)b * NPROP + n) * (NCLS * 4) + c * 4;
        float dx = dd[0] * 0.1f;
        float dy = dd[1] * 0.1f;
        float dw = fminf(fmaxf(dd[2] * 0.2f, -MAXR), MAXR);
        float dh = fminf(fmaxf(dd[3] * 0.2f, -MAXR), MAXR);
        float gw = pw * expf(dw);
        float gh = ph * expf(dh);
        float gx = px + pw * dx;
        float gy = py + ph * dy;
        float x1 = fminf(fmaxf(gx - 0.5f * gw, 0.f), w);
        float y1 = fminf(fmaxf(gy - 0.5f * gh, 0.f), h);
        float x2 = fminf(fmaxf(gx + 0.5f * gw, 0.f), w);
        float y2 = fminf(fmaxf(gy + 0.5f * gh, 0.f), h);
        float off = (float)c * offmul;
        sbxout[i] = make_float4(x1, y1, x2, y2);
        float4 sbv = make_float4(x1 + off, y1 + off, x2 + off, y2 + off);
        sbox[i] = sbv;
        sarea[i] = fmaxf(sbv.z - sbv.x, 0.f) * fmaxf(sbv.w - sbv.y, 0.f);
        slab[i] = (char)c;
        salive[i] = 1;
    }
    // class counts
    for (int i = tid; i < NCLS; i += NT) c_cnt[i] = 0;
    __syncthreads();
    for (int i = tid; i < validcnt; i += NT)
        atomicAdd(&c_cnt[(int)slab[i]], 1);
    __syncthreads();

    // ---- exclusive prefix over 80 class counts (warp 0) ----
    if (warp == 0) {
        int a = (lane < NCLS) ? c_cnt[lane] : 0;
        int b2 = (lane + 32 < NCLS) ? c_cnt[lane + 32] : 0;
        int c3 = (lane + 64 < NCLS) ? c_cnt[lane + 64] : 0;
        int sa = a, sb2 = b2, sc3 = c3;
#pragma unroll
        for (int o = 1; o < 32; o <<= 1) {
            int u = __shfl_up_sync(0xffffffffu, sa, o); if (lane >= o) sa += u;
            int u2 = __shfl_up_sync(0xffffffffu, sb2, o); if (lane >= o) sb2 += u2;
            int u3 = __shfl_up_sync(0xffffffffu, sc3, o); if (lane >= o) sc3 += u3;
        }
        int totA = __shfl_sync(0xffffffffu, sa, 31);
        int totB = __shfl_sync(0xffffffffu, sb2, 31);
        if (lane < NCLS) c_base[lane] = sa - a;
        if (lane + 32 < NCLS) c_base[lane + 32] = totA + sb2 - b2;
        if (lane + 64 < NCLS) c_base[lane + 64] = totA + totB + sc3 - c3;
    }
    __syncthreads();

    // ---- per-class member list + greedy NMS (one warp per class) ----
    for (int c = warp; c < NCLS; c += 32) {
        int cb = c_base[c];
        int n2 = 0;
        for (int k0 = 0; k0 < validcnt; k0 += 32) {
            int i = k0 + lane;
            bool mine = (i < validcnt) && ((int)slab[i] == c);
            unsigned mm = __ballot_sync(0xffffffffu, mine);
            if (mine) clist[cb + n2 + __popc(mm & ((1u << lane) - 1))] = i;
            n2 += __popc(mm);
        }
        __syncwarp(0xffffffffu);
        // greedy NMS within class (members already in score order)
        for (int s2 = 0; s2 < n2; s2++) {
            int is = clist[cb + s2];
            if (!salive[is]) continue;
            float4 A = sbox[is];
            float areaA = sarea[is];
            for (int t = s2 + 1 + lane; t < n2; t += 32) {
                int jt = clist[cb + t];
                if (!salive[jt]) continue;
                float4 q = sbox[jt];
                float inter = fmaxf(fminf(A.z, q.z) - fmaxf(A.x, q.x), 0.f) *
                              fmaxf(fminf(A.w, q.w) - fmaxf(A.y, q.y), 0.f);
                float uni = areaA + sarea[jt] - inter;
                if (uni > 0.f && inter > IOU_THR * uni) salive[jt] = 0;
            }
            __syncwarp(0xffffffffu);
        }
    }
    __syncthreads();

    // ---- prefix over keep flags, emit first 100 in sorted order ----
    int i0 = 2 * tid, i1 = 2 * tid + 1;
    int a0 = salive[i0], a1 = salive[i1];
    int ps = a0 + a1;
    int sc = ps;
#pragma unroll
    for (int o = 1; o < 32; o <<= 1) {
        int u = __shfl_up_sync(0xffffffffu, sc, o);
        if (lane >= o) sc += u;
    }
    if (lane == 31) s_wsum[warp] = sc;
    __syncthreads();
    if (warp == 0) {
        int wv = s_wsum[lane];
#pragma unroll
        for (int o = 1; o < 32; o <<= 1) {
            int u = __shfl_up_sync(0xffffffffu, wv, o);
            if (lane >= o) wv += u;
        }
        s_wsum[lane] = wv;
        if (lane == 31) s_total = wv;
    }
    __syncthreads();
    int wbase = warp ? s_wsum[warp - 1] : 0;
    int excl = wbase + sc - ps;

    if (a0 && excl < OUTK) {
        ull key = skey[i0];
        ((float4*)out)[b * OUTK + excl] = sbxout[i0];
        out[BATCH * OUTK * 4 + b * OUTK + excl] = __uint_as_float(~(unsigned)(key >> 32));
        out[BATCH * OUTK * 5 + b * OUTK + excl] = (float)((unsigned)key % NCLS);
    }
    int r1 = excl + a0;
    if (a1 && r1 < OUTK) {
        ull key = skey[i1];
        ((float4*)out)[b * OUTK + r1] = sbxout[i1];
        out[BATCH * OUTK * 4 + b * OUTK + r1] = __uint_as_float(~(unsigned)(key >> 32));
        out[BATCH * OUTK * 5 + b * OUTK + r1] = (float)((unsigned)key % NCLS);
    }
    int kept = min(s_total, OUTK);
    for (int r = kept + tid; r < OUTK; r += NT) {
        ((float4*)out)[b * OUTK + r] = make_float4(0.f, 0.f, 0.f, 0.f);
        out[BATCH * OUTK * 4 + b * OUTK + r] = 0.0f;
        out[BATCH * OUTK * 5 + b * OUTK + r] = -1.0f;
    }

    if (tid == 0) g_cnt[b] = 0;
}

// ---------------- launch ----------------
extern "C" void kernel_launch(void* const* d_in, const int* in_sizes, int n_in,
                              void* d_out, int out_size) {
    const float* cls = (const float*)d_in[0];   // [16,2048,81]
    const float* reg = (const float*)d_in[1];   // [16,2048,320]
    const float* props = (const float*)d_in[2]; // [16,2048,4]
    const int* hw = (const int*)d_in[3];        // [16,2]
    float* out = (float*)d_out;

    cudaFuncSetAttribute(k_fused,
                         cudaFuncAttributeMaxDynamicSharedMemorySize, SMEM_DYN);

    k_softmax_compact<<<BATCH * NPROP / 8, 256>>>(cls);
    k_fused<<<BATCH, NT, SMEM_DYN>>>(reg, props, hw, out);
}

// round 8
// speedup vs baseline: 2.7917x; 1.4745x over previous
#include <cuda_runtime.h>
#include <cstdint>

#define BATCH 16
#define NPROP 2048
#define NCLS 80
#define NCLS1 81
#define KTOP 2048
#define CAP 16384
#define SCORE_THR 0.05f
#define IOU_THR 0.5f
#define MAXR 4.135166556742356f
#define OUTK 100
#define HISTN 3072
#define BINS 2304
#define SLOTS 4096
#define NT 1024

typedef unsigned long long ull;
typedef unsigned char uchar;

// ---------------- device scratch ----------------
__device__ ull g_keys[BATCH][CAP];
__device__ int g_cnt[BATCH];          // zero-init; re-zeroed at end of k_select
__device__ ull g_skey[BATCH][KTOP];
__device__ int g_valid[BATCH];
__device__ float4 g_obox[BATCH][KTOP];   // offset boxes (NMS space)
__device__ float4 g_bout[BATCH][KTOP];   // clipped boxes (output space)
__device__ float g_area[BATCH][KTOP];
__device__ uchar g_lab[BATCH][KTOP];
__device__ uchar g_alive[BATCH][KTOP];

__device__ __forceinline__ int score_bin(unsigned u) {
    int bn = (int)(u >> 14) - 62770;
    return min(max(bn, 0), BINS - 1);
}

// ---------------- 1: softmax + threshold + block-aggregated compaction ----------------
__global__ void k_softmax_compact(const float* __restrict__ cls) {
    __shared__ int s_cnt, s_base;
    __shared__ ull s_buf[176];
    int tid = threadIdx.x;
    int lane = tid & 31;
    int w = tid >> 5;
    int gw = blockIdx.x * 8 + w;
    int b = gw >> 11;
    int n = gw & (NPROP - 1);

    if (tid == 0) s_cnt = 0;
    __syncthreads();

    const float* x = cls + (size_t)gw * NCLS1;
    float v0 = x[lane];
    float v1 = x[lane + 32];
    float v2 = (lane < 17) ? x[lane + 64] : -3.4e38f;
    float m = fmaxf(fmaxf(v0, v1), v2);
#pragma unroll
    for (int o = 16; o > 0; o >>= 1) m = fmaxf(m, __shfl_xor_sync(0xffffffffu, m, o));
    float e0 = expf(v0 - m);
    float e1 = expf(v1 - m);
    float e2 = (lane < 17) ? expf(v2 - m) : 0.0f;
    float s = e0 + e1 + e2;
#pragma unroll
    for (int o = 16; o > 0; o >>= 1) s += __shfl_xor_sync(0xffffffffu, s, o);

    auto push = [&](bool cond, float p, unsigned idx) {
        unsigned mask = __ballot_sync(0xffffffffu, cond);
        if (cond) {
            unsigned u = __float_as_uint(p);
            int leader = __ffs(mask) - 1;
            int base = 0;
            if (lane == leader) base = atomicAdd(&s_cnt, __popc(mask));
            base = __shfl_sync(mask, base, leader);
            s_buf[base + __popc(mask & ((1u << lane) - 1))] = ((ull)(~u) << 32) | idx;
        }
    };
    float p0 = e0 / s;
    push(p0 > SCORE_THR, p0, (unsigned)(n * NCLS + lane));
    float p1 = e1 / s;
    push(p1 > SCORE_THR, p1, (unsigned)(n * NCLS + lane + 32));
    float p2 = e2 / s;
    push((lane < 16) && (p2 > SCORE_THR), p2, (unsigned)(n * NCLS + lane + 64));
    __syncthreads();

    if (tid == 0) s_base = atomicAdd(&g_cnt[b], s_cnt);
    __syncthreads();
    int cnt = s_cnt, base = s_base;
    for (int i = tid; i < cnt; i += 256)
        if (base + i < CAP) g_keys[b][base + i] = s_buf[i];
}

// ---------------- 2: select (hist+scan+scatter+rank) + decode ----------------
// smem: skey 32768 | tmpk 32768 | hist 12288 | base 12288 = 90112
#define SMEM_SEL 90112
extern __shared__ char dynsel[];

__global__ void __launch_bounds__(NT) k_select(const float* __restrict__ reg,
                                               const float* __restrict__ props,
                                               const int* __restrict__ hw) {
    int b = blockIdx.x;
    int tid = threadIdx.x;
    int lane = tid & 31;
    int warp = tid >> 5;

    ull* skey = (ull*)dynsel;
    ull* tmpk = (ull*)(dynsel + 32768);
    int* hist = (int*)(dynsel + 65536);
    int* base = (int*)(dynsel + 77824);
    __shared__ int s_wsum[32];

    int cnt = min(g_cnt[b], CAP);

    for (int i = tid; i < HISTN; i += NT) hist[i] = 0;
    __syncthreads();
    for (int i = tid; i < cnt; i += NT)
        atomicAdd(&hist[score_bin(~(unsigned)(g_keys[b][i] >> 32))], 1);
    __syncthreads();

    // hierarchical suffix scan
    int h0 = hist[3 * tid], h1 = hist[3 * tid + 1], h2 = hist[3 * tid + 2];
    int loc = h0 + h1 + h2;
    int v = loc;
#pragma unroll
    for (int o = 1; o < 32; o <<= 1) {
        int u = __shfl_down_sync(0xffffffffu, v, o);
        if (lane + o < 32) v += u;
    }
    if (lane == 0) s_wsum[warp] = v;
    __syncthreads();
    if (warp == 0) {
        int wv = s_wsum[lane];
#pragma unroll
        for (int o = 1; o < 32; o <<= 1) {
            int u = __shfl_down_sync(0xffffffffu, wv, o);
            if (lane + o < 32) wv += u;
        }
        s_wsum[lane] = wv;
    }
    __syncthreads();
    int beyondW = (warp < 31) ? s_wsum[warp + 1] : 0;
    int beyond = v + beyondW - loc;
    base[3 * tid + 2] = beyond;
    base[3 * tid + 1] = beyond + h2;
    base[3 * tid] = beyond + h2 + h1;
    int S_total = s_wsum[0];
    __syncthreads();

    for (int i = tid; i < HISTN; i += NT) hist[i] = 0;
    __syncthreads();
    for (int i = tid; i < cnt; i += NT) {
        ull k = g_keys[b][i];
        int bb = score_bin(~(unsigned)(k >> 32));
        int st = base[bb];
        if (st >= SLOTS) continue;
        int pos = st + atomicAdd(&hist[bb], 1);
        if (pos < SLOTS) tmpk[pos] = k;
    }
    __syncthreads();

    int S_use = min(S_total, SLOTS);
    for (int i = tid; i < S_use; i += NT) {
        ull k = tmpk[i];
        int bb = score_bin(~(unsigned)(k >> 32));
        int st = base[bb];
        if (st >= KTOP) continue;
        int en = min(st + hist[bb], SLOTS);
        int r = 0;
        for (int j = st; j < en; j++) r += (tmpk[j] < k);
        int pos = st + r;
        if (pos < SLOTS) skey[pos] = k;
    }
    __syncthreads();

    int validcnt = min(S_total, KTOP);
    if (tid == 0) { g_valid[b] = validcnt; g_cnt[b] = 0; }

    // ---- decode + write globals ----
    float h = (float)hw[b * 2];
    float w = (float)hw[b * 2 + 1];
    float offmul = fmaxf(w, h) + 1.0f;

    for (int i = tid; i < KTOP; i += NT) {
        if (i >= validcnt) {
            g_lab[b][i] = 255;
            g_alive[b][i] = 0;
            continue;
        }
        ull key = skey[i];
        g_skey[b][i] = key;
        unsigned idx = (unsigned)key;
        int n = (int)(idx / NCLS);
        int c = (int)(idx % NCLS);
        const float* pr = props + ((size_t)b * NPROP + n) * 4;
        float p0 = pr[0], p1 = pr[1], p2 = pr[2], p3 = pr[3];
        float px = (p0 + p2) * 0.5f;
        float py = (p1 + p3) * 0.5f;
        float pw = p2 - p0;
        float ph = p3 - p1;
        const float* dd = reg + ((size_t)b * NPROP + n) * (NCLS * 4) + c * 4;
        float dx = dd[0] * 0.1f;
        float dy = dd[1] * 0.1f;
        float dw = fminf(fmaxf(dd[2] * 0.2f, -MAXR), MAXR);
        float dh = fminf(fmaxf(dd[3] * 0.2f, -MAXR), MAXR);
        float gw = pw * expf(dw);
        float gh = ph * expf(dh);
        float gx = px + pw * dx;
        float gy = py + ph * dy;
        float x1 = fminf(fmaxf(gx - 0.5f * gw, 0.f), w);
        float y1 = fminf(fmaxf(gy - 0.5f * gh, 0.f), h);
        float x2 = fminf(fmaxf(gx + 0.5f * gw, 0.f), w);
        float y2 = fminf(fmaxf(gy + 0.5f * gh, 0.f), h);
        float off = (float)c * offmul;
        g_bout[b][i] = make_float4(x1, y1, x2, y2);
        float4 sbv = make_float4(x1 + off, y1 + off, x2 + off, y2 + off);
        g_obox[b][i] = sbv;
        g_area[b][i] = fmaxf(sbv.z - sbv.x, 0.f) * fmaxf(sbv.w - sbv.y, 0.f);
        g_lab[b][i] = (uchar)c;
        g_alive[b][i] = 1;
    }
}

// ---------------- 3: per-class NMS, one warp per (image, class) ----------------
// grid = BATCH*10 blocks, 256 threads (8 warps); block = (b, class-group of 8)
// smem: boxes 32768 | area 8192 | clist(short) 4096 | lab 2048 | alive 2048 = 49152
#define SMEM_NMS 49152
extern __shared__ char dynnms[];

__global__ void __launch_bounds__(256) k_nms() {
    int b = blockIdx.x / 10;
    int cg = blockIdx.x % 10;
    int tid = threadIdx.x;
    int lane = tid & 31;
    int warp = tid >> 5;

    float4* sb = (float4*)dynnms;
    float* sar = (float*)(dynnms + 32768);
    short* clist = (short*)(dynnms + 40960);
    uchar* slab = (uchar*)(dynnms + 45056);
    uchar* salive = (uchar*)(dynnms + 47104);
    __shared__ int s_cnt[8], s_base[8];

    int valid = g_valid[b];

    for (int i = tid; i < KTOP; i += 256) {
        sb[i] = g_obox[b][i];
        sar[i] = g_area[b][i];
        slab[i] = g_lab[b][i];
        salive[i] = g_alive[b][i];
    }
    __syncthreads();

    int c = cg * 8 + warp;
    // count members
    int n2 = 0;
    for (int k0 = 0; k0 < valid; k0 += 32) {
        int i = k0 + lane;
        bool mine = (i < valid) && ((int)slab[i] == c);
        n2 += __popc(__ballot_sync(0xffffffffu, mine));
    }
    if (lane == 0) s_cnt[warp] = n2;
    __syncthreads();
    if (tid == 0) {
        int acc = 0;
        for (int k = 0; k < 8; k++) { s_base[k] = acc; acc += s_cnt[k]; }
    }
    __syncthreads();
    int cb = s_base[warp];

    // compact member indices (sorted order preserved)
    int wr = 0;
    for (int k0 = 0; k0 < valid; k0 += 32) {
        int i = k0 + lane;
        bool mine = (i < valid) && ((int)slab[i] == c);
        unsigned mm = __ballot_sync(0xffffffffu, mine);
        if (mine) clist[cb + wr + __popc(mm & ((1u << lane) - 1))] = (short)i;
        wr += __popc(mm);
    }
    __syncwarp(0xffffffffu);

    // greedy NMS within class
    for (int s2 = 0; s2 < n2; s2++) {
        int is = clist[cb + s2];
        if (!salive[is]) continue;
        float4 A = sb[is];
        float areaA = sar[is];
        for (int t = s2 + 1 + lane; t < n2; t += 32) {
            int jt = clist[cb + t];
            if (!salive[jt]) continue;
            float4 q = sb[jt];
            float inter = fmaxf(fminf(A.z, q.z) - fmaxf(A.x, q.x), 0.f) *
                          fmaxf(fminf(A.w, q.w) - fmaxf(A.y, q.y), 0.f);
            float uni = areaA + sar[jt] - inter;
            if (uni > 0.f && inter > IOU_THR * uni) {
                salive[jt] = 0;
                g_alive[b][jt] = 0;
            }
        }
        __syncwarp(0xffffffffu);
    }
}

// ---------------- 4: prefix over keep flags + emit top-100 ----------------
__global__ void __launch_bounds__(NT) k_out(float* __restrict__ out) {
    int b = blockIdx.x;
    int tid = threadIdx.x;
    int lane = tid & 31;
    int warp = tid >> 5;
    __shared__ int s_wsum[32];
    __shared__ int s_total;

    int i0 = 2 * tid, i1 = 2 * tid + 1;
    int a0 = g_alive[b][i0], a1 = g_alive[b][i1];
    int ps = a0 + a1;
    int sc = ps;
#pragma unroll
    for (int o = 1; o < 32; o <<= 1) {
        int u = __shfl_up_sync(0xffffffffu, sc, o);
        if (lane >= o) sc += u;
    }
    if (lane == 31) s_wsum[warp] = sc;
    __syncthreads();
    if (warp == 0) {
        int wv = s_wsum[lane];
#pragma unroll
        for (int o = 1; o < 32; o <<= 1) {
            int u = __shfl_up_sync(0xffffffffu, wv, o);
            if (lane >= o) wv += u;
        }
        s_wsum[lane] = wv;
        if (lane == 31) s_total = wv;
    }
    __syncthreads();
    int wbase = warp ? s_wsum[warp - 1] : 0;
    int excl = wbase + sc - ps;

    if (a0 && excl < OUTK) {
        ull key = g_skey[b][i0];
        ((float4*)out)[b * OUTK + excl] = g_bout[b][i0];
        out[BATCH * OUTK * 4 + b * OUTK + excl] = __uint_as_float(~(unsigned)(key >> 32));
        out[BATCH * OUTK * 5 + b * OUTK + excl] = (float)((unsigned)key % NCLS);
    }
    int r1 = excl + a0;
    if (a1 && r1 < OUTK) {
        ull key = g_skey[b][i1];
        ((float4*)out)[b * OUTK + r1] = g_bout[b][i1];
        out[BATCH * OUTK * 4 + b * OUTK + r1] = __uint_as_float(~(unsigned)(key >> 32));
        out[BATCH * OUTK * 5 + b * OUTK + r1] = (float)((unsigned)key % NCLS);
    }
    int kept = min(s_total, OUTK);
    for (int r = kept + tid; r < OUTK; r += NT) {
        ((float4*)out)[b * OUTK + r] = make_float4(0.f, 0.f, 0.f, 0.f);
        out[BATCH * OUTK * 4 + b * OUTK + r] = 0.0f;
        out[BATCH * OUTK * 5 + b * OUTK + r] = -1.0f;
    }
}

// ---------------- launch ----------------
extern "C" void kernel_launch(void* const* d_in, const int* in_sizes, int n_in,
                              void* d_out, int out_size) {
    const float* cls = (const float*)d_in[0];   // [16,2048,81]
    const float* reg = (const float*)d_in[1];   // [16,2048,320]
    const float* props = (const float*)d_in[2]; // [16,2048,4]
    const int* hw = (const int*)d_in[3];        // [16,2]
    float* out = (float*)d_out;

    cudaFuncSetAttribute(k_select,
                         cudaFuncAttributeMaxDynamicSharedMemorySize, SMEM_SEL);
    cudaFuncSetAttribute(k_nms,
                         cudaFuncAttributeMaxDynamicSharedMemorySize, SMEM_NMS);

    k_softmax_compact<<<BATCH * NPROP / 8, 256>>>(cls);
    k_select<<<BATCH, NT, SMEM_SEL>>>(reg, props, hw);
    k_nms<<<BATCH * 10, 256, SMEM_NMS>>>();
    k_out<<<BATCH, NT>>>(out);
}